// round 7
// baseline (speedup 1.0000x reference)
#include <cuda_runtime.h>

#define L      2048
#define BATCH  512
#define NDIM   128

#define TT 64
#define BB 64
#define TS 64
#define US 66
#define CH 64          // staged rows per chunk (64*128*4 = 32 KB)
#define NBLK 80        // fused pipeline grid (<= 148 SMs -> co-resident)

typedef unsigned long long u64;

// ---------------- scratch (__device__ globals, allocation-free) ----------------
__device__ __align__(16) float g_S[2][NDIM * NDIM];  // A^(2^k) chain, ping-pong
__device__ __align__(16) float g_R[2][NDIM * NDIM];  // (A^(64*2^k))^T chain
__device__ __align__(16) float g_W[64 * NDIM];       // w_j = (A^T)^j B
__device__ __align__(16) float g_Y[32 * NDIM];       // y_i = A^(64 i) C
__device__ float g_h[L];                             // h_n = B A^n C
__device__ unsigned g_cnt = 0;                       // barrier count (self-reset)
__device__ unsigned g_gen = 0;                       // barrier generation

// ---------------------------------------------------------------------------
// Grid-wide sense-reversing barrier. Safe: all NBLK blocks are co-resident
// (NBLK <= #SMs, 1 block/SM). Replay-deterministic: cnt ends at 0, gen is
// monotonic and only compared for change.
// ---------------------------------------------------------------------------
__device__ __forceinline__ void gbar()
{
    __syncthreads();
    if (threadIdx.x == 0) {
        __threadfence();                                   // release
        unsigned g = *(volatile unsigned*)&g_gen;          // snapshot BEFORE arrive
        unsigned old = atomicAdd(&g_cnt, 1);
        if (old == NBLK - 1) {
            g_cnt = 0;                                     // no concurrent access here
            __threadfence();
            atomicAdd(&g_gen, 1);
        } else {
            while (*(volatile unsigned*)&g_gen == g) __nanosleep(32);
        }
        __threadfence();                                   // acquire
    }
    __syncthreads();
}

// ---------------------------------------------------------------------------
// Block-cooperative column dot: sum_k shrow[k] * M[k*NDIM + col].
// M streamed through smem in CH-row chunks (independent float4 fills).
// Must be reached by ALL 256 threads of the block (has __syncthreads).
// ---------------------------------------------------------------------------
__device__ __forceinline__ float staged_dot(const float* __restrict__ M,
                                            const float* shrow,
                                            float* tile, int tid, int col)
{
    float a0 = 0.f, a1 = 0.f, a2 = 0.f, a3 = 0.f;
#pragma unroll
    for (int kk = 0; kk < NDIM; kk += CH) {
        __syncthreads();
        const float4* src = (const float4*)(M + kk * NDIM);
        float4* dst = (float4*)tile;
#pragma unroll
        for (int p = 0; p < (CH * NDIM / 4) / 256; ++p)    // 8 indep float4
            dst[p * 256 + tid] = src[p * 256 + tid];
        __syncthreads();
#pragma unroll
        for (int q = 0; q < CH; q += 4) {
            a0 += shrow[kk + q + 0] * tile[(q + 0) * NDIM + col];
            a1 += shrow[kk + q + 1] * tile[(q + 1) * NDIM + col];
            a2 += shrow[kk + q + 2] * tile[(q + 2) * NDIM + col];
            a3 += shrow[kk + q + 3] * tile[(q + 3) * NDIM + col];
        }
    }
    return (a0 + a1) + (a2 + a3);
}

// ---------------------------------------------------------------------------
// Fused h-pipeline: one launch, 11 global barriers.
//  W phase k (k=0..5): blocks 0-63 square S_k (2 rows each); blocks 64+ expand
//    w_{2^k+j} = (A^T)^{2^k} w_j (2 vectors each). k==5 squaring writes R_0^T.
//  Y phase k (k=0..4): same in transposed (R) space for y_i = A^(64 i) C.
//  Final: h[64 i + j] = w_j . y_i  (blocks 0-31).
// ---------------------------------------------------------------------------
__global__ __launch_bounds__(256) void hpipe_kernel(const float* __restrict__ Af,
                                                    const float* __restrict__ Bf,
                                                    const float* __restrict__ Cf)
{
    __shared__ float sh[2][NDIM];
    __shared__ __align__(16) float tile[CH * NDIM];
    const int tid  = threadIdx.x;
    const int half = tid >> 7;
    const int col  = tid & 127;
    const int b    = blockIdx.x;

    // ---------------- W phases ----------------
#pragma unroll 1
    for (int k = 0; k <= 5; ++k) {
        const int m = 1 << k;
        const float* M = (k == 0) ? Af : g_S[k & 1];
        if (b < 64) {                          // ---- squaring, rows 2b, 2b+1 ----
            const int r = 2 * b + half;
            sh[half][col] = M[r * NDIM + col];
            float acc = staged_dot(M, sh[half], tile, tid, col);
            if (k == 5) g_R[0][col * NDIM + r] = acc;       // R_0 = (A^64)^T
            else        g_S[(k + 1) & 1][r * NDIM + col] = acc;
        } else {                               // ---- expand W ----
            const int j0 = 2 * (b - 64);
            if (j0 < m) {                      // uniform per block
                const int j = j0 + half;
                if (k == 0) {
                    sh[half][col] = Bf[col];   // both halves defined; half1 unused
                    if (half == 0) { g_W[col] = Bf[col]; g_Y[col] = Cf[col]; }
                } else if (j < m) {
                    sh[half][col] = g_W[j * NDIM + col];
                }
                float acc = staged_dot(M, sh[half], tile, tid, col);
                if (j < m) g_W[(m + j) * NDIM + col] = acc;
            }
        }
        gbar();
    }

    // ---------------- Y phases ----------------
#pragma unroll 1
    for (int k = 0; k <= 4; ++k) {
        const int m = 1 << k;
        const float* R = g_R[k & 1];
        if (k < 4 && b < 64) {                 // ---- squaring R ----
            const int r = 2 * b + half;
            sh[half][col] = R[r * NDIM + col];
            float acc = staged_dot(R, sh[half], tile, tid, col);
            g_R[(k + 1) & 1][r * NDIM + col] = acc;
        } else if (b >= 64) {                  // ---- expand Y ----
            const int j0 = 2 * (b - 64);
            if (j0 < m) {
                const int j = j0 + half;
                if (j < m) sh[half][col] = g_Y[j * NDIM + col];
                float acc = staged_dot(R, sh[half], tile, tid, col);
                if (j < m) g_Y[(m + j) * NDIM + col] = acc;
            }
        }
        gbar();
    }

    // ---------------- hdot: h[64 i + j] = w_j . y_i ----------------
    if (b < 32) {
        float* ys = tile;                      // reuse smem
        if (tid < NDIM) ys[tid] = g_Y[b * NDIM + tid];
        __syncthreads();
        const int j = tid >> 2, q = tid & 3;
        const float* __restrict__ w = &g_W[j * NDIM + q * 32];
        const float* __restrict__ y = &ys[q * 32];
        float p0 = 0.f, p1 = 0.f;
#pragma unroll
        for (int c = 0; c < 32; c += 2) { p0 += w[c] * y[c]; p1 += w[c + 1] * y[c + 1]; }
        float p = p0 + p1;
        p += __shfl_xor_sync(0xFFFFFFFFu, p, 1);
        p += __shfl_xor_sync(0xFFFFFFFFu, p, 2);
        if (q == 0) g_h[b * 64 + j] = p;
    }
}

// ---------------------------------------------------------------------------
// Packed f32x2 helpers (exact fp32 FMA semantics)
// ---------------------------------------------------------------------------
__device__ __forceinline__ void ffma2(u64& d, u64 a, u64 b)
{
    asm("fma.rn.f32x2 %0, %1, %2, %0;" : "+l"(d) : "l"(a), "l"(b));
}
__device__ __forceinline__ u64 splat2(float x)
{
    u64 r; asm("mov.b64 %0, {%1, %1};" : "=l"(r) : "f"(x)); return r;
}
__device__ __forceinline__ void unpack2(u64 v, float& lo, float& hi)
{
    asm("mov.b64 {%0, %1}, %2;" : "=f"(lo), "=f"(hi) : "l"(v));
}

// ---------------------------------------------------------------------------
// Causal Toeplitz conv: out[b,t] = f_t * sum_{s<=t} h[t-s] u[b,s] + D u[b,t]
// (unchanged from round 6 — measured at FFMA2 roofline)
// ---------------------------------------------------------------------------
__global__ __launch_bounds__(128) void conv_kernel(const float* __restrict__ u,
                                                   const float* __restrict__ Dp,
                                                   float* __restrict__ out)
{
    __shared__ __align__(16) float Us[TS][US];   // [ss][bb]
    __shared__ float hsArr[132];
    float* hsp = hsArr + 4;

    const int z     = blockIdx.x;
    const int tileT = 31 - (z >> 3);        // heaviest first
    const int t0    = tileT * TT;
    const int b0    = (z & 7) * BB;
    const int tid   = threadIdx.x;
    const int tx    = tid & 7;
    const int ty    = tid >> 3;
    const int tt0   = tx * 8;
    const int bb0   = ty * 4;

    u64 acc2[8][2];
#pragma unroll
    for (int r = 0; r < 8; ++r) { acc2[r][0] = 0ull; acc2[r][1] = 0ull; }

    if (tid < 4) hsArr[tid] = 0.0f;         // guards hsp[-4..-1]

    for (int st = 0; st <= tileT; ++st) {
        const int s0 = st * TS;
        __syncthreads();
        {   // h window: hsp[d] = h[t0-s0-63+d], zero OOB
            int g = t0 - s0 - 63 + tid;
            hsp[tid] = (g >= 0 && g < L) ? g_h[g] : 0.0f;
        }
#pragma unroll
        for (int p = 0; p < 32; ++p) {      // coalesced LDG fill
            int f  = p * 128 + tid;
            int bb = f >> 6;
            int ss = f & 63;
            Us[ss][bb] = u[(size_t)(b0 + bb) * L + (s0 + ss)];
        }
        __syncthreads();

        u64 w2[8];
#pragma unroll
        for (int r = 0; r < 8; ++r) w2[r] = splat2(hsp[tt0 + 63 + r]);

#pragma unroll
        for (int ss = 0; ss < TS; ++ss) {
            u64 u01 = *(const u64*)&Us[ss][bb0];
            u64 u23 = *(const u64*)&Us[ss][bb0 + 2];
#pragma unroll
            for (int r = 0; r < 8; ++r) {
                ffma2(acc2[r][0], u01, w2[r]);
                ffma2(acc2[r][1], u23, w2[r]);
            }
            float nw = hsp[tt0 + 62 - ss];  // hsp[-1] is zeroed guard
#pragma unroll
            for (int r = 7; r > 0; --r) w2[r] = w2[r - 1];
            w2[0] = splat2(nw);
        }
    }

    const float Dv = Dp[0];
#pragma unroll
    for (int r = 0; r < 8; ++r) {
        const int t = t0 + tt0 + r;
        const float f = (t == 0) ? 1.0f : 2.0f;
#pragma unroll
        for (int p = 0; p < 2; ++p) {
            float lo, hi;
            unpack2(acc2[r][p], lo, hi);
            const int b = b0 + bb0 + 2 * p;
            const size_t o0 = (size_t)b * L + t;
            const size_t o1 = (size_t)(b + 1) * L + t;
            out[o0] = f * lo + Dv * u[o0];
            out[o1] = f * hi + Dv * u[o1];
        }
    }
}

// ---------------------------------------------------------------------------
extern "C" void kernel_launch(void* const* d_in, const int* in_sizes, int n_in,
                              void* d_out, int out_size)
{
    const float* u  = (const float*)d_in[0];  // (512, 2048)
    const float* A  = (const float*)d_in[1];  // (128, 128)
    const float* B  = (const float*)d_in[2];  // (128,)
    const float* Cd = (const float*)d_in[3];  // (128,)
    const float* Dd = (const float*)d_in[4];  // (1,)
    float* out = (float*)d_out;               // (512, 2048)

    hpipe_kernel<<<NBLK, 256>>>(A, B, Cd);
    conv_kernel<<<256, 128>>>(u, Dd, out);
}

// round 9
// speedup vs baseline: 1.1799x; 1.1799x over previous
#include <cuda_runtime.h>

#define L      2048
#define BATCH  512
#define NDIM   128

#define TT 64
#define BB 64
#define TS 64
#define US 66
#define CH 64          // staged rows per chunk in h-pipeline (32 KB)
#define CHS 8          // s-tiles per conv chunk (split-K)

typedef unsigned long long u64;

// ---------------- scratch (__device__ globals, allocation-free) ----------------
__device__ __align__(16) float g_S[2][NDIM * NDIM];  // A^(2^k) chain, ping-pong
__device__ __align__(16) float g_R[2][NDIM * NDIM];  // (A^(64*2^k))^T chain
__device__ __align__(16) float g_W[64 * NDIM];       // w_j = (A^T)^j B
__device__ __align__(16) float g_Y[32 * NDIM];       // y_i = A^(64 i) C
__device__ float g_h[L];                             // h_n = B A^n C
__device__ __align__(16) float g_part[4][BATCH * L]; // split-K partials (16 MB)

// ---------------------------------------------------------------------------
// Block-cooperative fp32 column dot (h-pipeline), matrix staged via smem.
// ---------------------------------------------------------------------------
__device__ __forceinline__ float staged_col_dot(const float* __restrict__ M,
                                                const float* sh,
                                                float* tile, int tid)
{
    float a0 = 0.f, a1 = 0.f, a2 = 0.f, a3 = 0.f;
#pragma unroll
    for (int kk = 0; kk < NDIM; kk += CH) {
        __syncthreads();
        const float4* src = (const float4*)(M + kk * NDIM);
        float4* dst = (float4*)tile;
#pragma unroll
        for (int p = 0; p < (CH * NDIM / 4) / 128; ++p)
            dst[p * 128 + tid] = src[p * 128 + tid];
        __syncthreads();
#pragma unroll
        for (int q = 0; q < CH; q += 4) {
            a0 += sh[kk + q + 0] * tile[(q + 0) * NDIM + tid];
            a1 += sh[kk + q + 1] * tile[(q + 1) * NDIM + tid];
            a2 += sh[kk + q + 2] * tile[(q + 2) * NDIM + tid];
            a3 += sh[kk + q + 3] * tile[(q + 3) * NDIM + tid];
        }
    }
    return (a0 + a1) + (a2 + a3);
}

// Stage k of W phase (k=0..5): blocks [0,128) square S_k (k==5 -> R_0^T);
// blocks [128,128+2^k) expand w; block 129 (k==0) seeds y_0 = C.
__global__ __launch_bounds__(128) void stageW_kernel(int k,
                                                     const float* __restrict__ Af,
                                                     const float* __restrict__ Bf,
                                                     const float* __restrict__ Cf)
{
    __shared__ float sh[NDIM];
    __shared__ __align__(16) float tile[CH * NDIM];
    const int tid = threadIdx.x;
    const float* M = (k == 0) ? Af : g_S[k & 1];

    if (blockIdx.x < 128) {
        const int r = blockIdx.x;
        sh[tid] = M[r * NDIM + tid];
        float acc = staged_col_dot(M, sh, tile, tid);
        if (k == 5) g_R[0][tid * NDIM + r] = acc;
        else        g_S[(k + 1) & 1][r * NDIM + tid] = acc;
    } else if ((int)blockIdx.x < 128 + (1 << k)) {
        const int j = blockIdx.x - 128;
        const int m = 1 << k;
        if (k == 0) { float b = Bf[tid]; g_W[tid] = b; sh[tid] = b; }
        else        sh[tid] = g_W[j * NDIM + tid];
        float acc = staged_col_dot(M, sh, tile, tid);
        g_W[(m + j) * NDIM + tid] = acc;
    } else {
        g_Y[tid] = Cf[tid];
    }
}

// Stage k of Y phase (k=0..4), in transposed (R) space.
__global__ __launch_bounds__(128) void stageY_kernel(int k)
{
    __shared__ float sh[NDIM];
    __shared__ __align__(16) float tile[CH * NDIM];
    const int tid = threadIdx.x;
    const float* R = g_R[k & 1];

    if (k < 4 && blockIdx.x < 128) {
        const int r = blockIdx.x;
        sh[tid] = R[r * NDIM + tid];
        g_R[(k + 1) & 1][r * NDIM + tid] = staged_col_dot(R, sh, tile, tid);
    } else {
        const int j = (k < 4) ? (int)blockIdx.x - 128 : (int)blockIdx.x;
        const int m = 1 << k;
        sh[tid] = g_Y[j * NDIM + tid];
        g_Y[(m + j) * NDIM + tid] = staged_col_dot(R, sh, tile, tid);
    }
}

// h[64*i + j] = w_j . y_i
__global__ void hdot_kernel()
{
    __shared__ float ys[NDIM];
    const int i = blockIdx.x;
    const int tid = threadIdx.x;
    if (tid < NDIM) ys[tid] = g_Y[i * NDIM + tid];
    __syncthreads();
    const int j = tid >> 2, q = tid & 3;
    const float* __restrict__ w = &g_W[j * NDIM + q * 32];
    const float* __restrict__ y = &ys[q * 32];
    float p0 = 0.f, p1 = 0.f;
#pragma unroll
    for (int c = 0; c < 32; c += 2) { p0 += w[c] * y[c]; p1 += w[c + 1] * y[c + 1]; }
    float p = p0 + p1;
    p += __shfl_xor_sync(0xFFFFFFFFu, p, 1);
    p += __shfl_xor_sync(0xFFFFFFFFu, p, 2);
    if (q == 0) g_h[i * 64 + j] = p;
}

// ---------------------------------------------------------------------------
// Packed f32x2 helpers
// ---------------------------------------------------------------------------
__device__ __forceinline__ void ffma2(u64& d, u64 a, u64 b)
{
    asm("fma.rn.f32x2 %0, %1, %2, %0;" : "+l"(d) : "l"(a), "l"(b));
}
__device__ __forceinline__ u64 splat2(float x)
{
    u64 r; asm("mov.b64 %0, {%1, %1};" : "=l"(r) : "f"(x)); return r;
}
__device__ __forceinline__ void unpack2(u64 v, float& lo, float& hi)
{
    asm("mov.b64 {%0, %1}, %2;" : "=f"(lo), "=f"(hi) : "l"(v));
}

// ---------------------------------------------------------------------------
// Split-K causal Toeplitz conv: each block covers one (t-tile, s-chunk, b-tile),
// s-chunk = up to CHS s-tiles; partial -> g_part[chunk]. 640 balanced blocks.
// ---------------------------------------------------------------------------
__global__ __launch_bounds__(128) void conv_kernel(const float* __restrict__ u)
{
    __shared__ __align__(16) float Us[TS][US];   // [ss][bb]
    __shared__ float hsArr[132];
    float* hsp = hsArr + 4;

    // decode blockIdx -> (tileT, chunk, bslice); heaviest t-tiles first
    int bs = blockIdx.x & 7;
    int q  = blockIdx.x >> 3;            // 0..79
    int tileT = 31;
    while (true) { int n = (tileT + 8) >> 3; if (q < n) break; q -= n; --tileT; }
    const int chunk = q;                 // 0..3
    const int t0    = tileT * TT;
    const int b0    = bs * BB;
    const int stLo  = chunk * CHS;
    const int stHi  = min(stLo + CHS - 1, tileT);

    const int tid = threadIdx.x;
    const int tx  = tid & 7;
    const int ty  = tid >> 3;
    const int tt0 = tx * 8;
    const int bb0 = ty * 4;

    u64 acc2[8][2];
#pragma unroll
    for (int r = 0; r < 8; ++r) { acc2[r][0] = 0ull; acc2[r][1] = 0ull; }

    if (tid < 4) hsArr[tid] = 0.0f;      // guards hsp[-4..-1]

    for (int st = stLo; st <= stHi; ++st) {
        const int s0 = st * TS;
        __syncthreads();
        {   // h window: hsp[d] = h[t0-s0-63+d], zero OOB
            int g = t0 - s0 - 63 + tid;
            hsp[tid] = (g >= 0 && g < L) ? g_h[g] : 0.0f;
        }
#pragma unroll
        for (int p = 0; p < 32; ++p) {   // coalesced LDG fill
            int f  = p * 128 + tid;
            int bb = f >> 6;
            int ss = f & 63;
            Us[ss][bb] = u[(size_t)(b0 + bb) * L + (s0 + ss)];
        }
        __syncthreads();

        u64 w2[8];
#pragma unroll
        for (int r = 0; r < 8; ++r) w2[r] = splat2(hsp[tt0 + 63 + r]);

#pragma unroll
        for (int ss = 0; ss < TS; ++ss) {
            u64 u01 = *(const u64*)&Us[ss][bb0];
            u64 u23 = *(const u64*)&Us[ss][bb0 + 2];
#pragma unroll
            for (int r = 0; r < 8; ++r) {
                ffma2(acc2[r][0], u01, w2[r]);
                ffma2(acc2[r][1], u23, w2[r]);
            }
            float nw = hsp[tt0 + 62 - ss];
#pragma unroll
            for (int r = 7; r > 0; --r) w2[r] = w2[r - 1];
            w2[0] = splat2(nw);
        }
    }

    float* __restrict__ part = g_part[chunk];
#pragma unroll
    for (int r = 0; r < 8; ++r) {
        const int t = t0 + tt0 + r;
#pragma unroll
        for (int p = 0; p < 2; ++p) {
            float lo, hi;
            unpack2(acc2[r][p], lo, hi);
            const int b = b0 + bb0 + 2 * p;
            part[(size_t)b * L + t]       = lo;
            part[(size_t)(b + 1) * L + t] = hi;
        }
    }
}

// ---------------------------------------------------------------------------
// Reduce: out = f_t * sum_{c<nch(t)} part[c] + D*u.  float4 over t.
// FIX: factor predicate is t==0 (per-row time index), NOT e0==0 (global idx).
// ---------------------------------------------------------------------------
__global__ __launch_bounds__(256) void reduce_kernel(const float* __restrict__ u,
                                                     const float* __restrict__ Dp,
                                                     float* __restrict__ out)
{
    const int idx = blockIdx.x * 256 + threadIdx.x;   // float4 index
    const int e0  = idx * 4;
    const int t   = e0 & (L - 1);                     // time index of lane .x
    const int nch = ((t >> 6) + 8) >> 3;              // ceil((tileT+1)/8)

    float4 s = ((const float4*)g_part[0])[idx];
    if (nch > 1) { float4 v = ((const float4*)g_part[1])[idx];
                   s.x += v.x; s.y += v.y; s.z += v.z; s.w += v.w; }
    if (nch > 2) { float4 v = ((const float4*)g_part[2])[idx];
                   s.x += v.x; s.y += v.y; s.z += v.z; s.w += v.w; }
    if (nch > 3) { float4 v = ((const float4*)g_part[3])[idx];
                   s.x += v.x; s.y += v.y; s.z += v.z; s.w += v.w; }

    const float Dv = Dp[0];
    float4 uu = ((const float4*)u)[idx];
    float4 o;
    // e0 is a multiple of 4, so only lane .x can be t==0 (t = e0 mod 2048);
    // lanes .y/.z/.w have t in {1,2,3} mod 2048 -> always factor 2.
    o.x = ((t == 0) ? 1.0f : 2.0f) * s.x + Dv * uu.x;
    o.y = 2.0f * s.y + Dv * uu.y;
    o.z = 2.0f * s.z + Dv * uu.z;
    o.w = 2.0f * s.w + Dv * uu.w;
    ((float4*)out)[idx] = o;
}

// ---------------------------------------------------------------------------
extern "C" void kernel_launch(void* const* d_in, const int* in_sizes, int n_in,
                              void* d_out, int out_size)
{
    const float* u  = (const float*)d_in[0];  // (512, 2048)
    const float* A  = (const float*)d_in[1];  // (128, 128)
    const float* B  = (const float*)d_in[2];  // (128,)
    const float* Cd = (const float*)d_in[3];  // (128,)
    const float* Dd = (const float*)d_in[4];  // (1,)
    float* out = (float*)d_out;               // (512, 2048)

    for (int k = 0; k <= 5; ++k) {
        int grid = (k == 0) ? 130 : 128 + (1 << k);
        stageW_kernel<<<grid, 128>>>(k, A, B, Cd);
    }
    for (int k = 0; k <= 4; ++k) {
        int grid = (k < 4) ? 128 + (1 << k) : 16;
        stageY_kernel<<<grid, 128>>>(k);
    }
    hdot_kernel<<<32, 256>>>();

    conv_kernel<<<640, 128>>>(u);                       // split-K partials
    reduce_kernel<<<(BATCH * L / 4) / 256, 256>>>(u, Dd, out);
}